// round 9
// baseline (speedup 1.0000x reference)
#include <cuda_runtime.h>
#include <cstdint>
#include <cstddef>

// x:   [B=8192, F=32, E=64] f32
// W:   [E=64, E=64] f32
// out: [B, P=496, E=64] f32,  out[b,p,:] = (x[b,i_p,:] @ W) * x[b,j_p,:]
// (i_p, j_p) = triu_indices(32, k=1), row-major pair order.

#define BB 8192
#define FF 32
#define EE 64
#define PP 496
#define NV4 (PP * (EE/4)) // 7936 float4 per batch row
#define NTHREADS 256
#define ROWS_PER_BLK 4
#define NBLK (BB / ROWS_PER_BLK) // 2048

// pairs before row i: sum_{t<i} (31-t) = 31*i - i*(i-1)/2
__device__ __forceinline__ int rowstart(int i) {
    return 31 * i - (i * (i - 1)) / 2;
}

__device__ __forceinline__ float4 fmul4(float4 a, float4 c) {
    float4 r;
    r.x = a.x * c.x; r.y = a.y * c.y; r.z = a.z * c.z; r.w = a.w * c.w;
    return r;
}

__device__ __forceinline__ void cp_async16(uint32_t smem_addr, const void* gptr) {
    asm volatile("cp.async.ca.shared.global [%0], [%1], 16;"
                 :: "r"(smem_addr), "l"(gptr));
}
__device__ __forceinline__ void cp_async_commit() {
    asm volatile("cp.async.commit_group;" ::: "memory");
}
__device__ __forceinline__ void cp_async_wait0() {
    asm volatile("cp.async.wait_group 0;" ::: "memory");
}

// Store one batch row: 16 groups of 16 lanes; group g owns rows i1=g
// (31-g pairs) and i2=30-g (g+1 pairs); g==15 owns only row 15.
// Inner body: 1 LDS.128 + 1 STG.128; 256B-contiguous group stores.
__device__ __forceinline__ void store_rows(const float4* __restrict__ xw4,
                                           const float4* __restrict__ xs4,
                                           float4* __restrict__ og,
                                           int g, int v)
{
    {
        const int i = g;
        const float4 a = xw4[i * 16 + v];
        float4* o = og + (ptrdiff_t)(rowstart(i) - i - 1) * 16 + v;
        #pragma unroll 4
        for (int j = i + 1; j < FF; ++j)
            __stcs(o + j * 16, fmul4(a, xs4[j * 16 + v]));
    }
    if (g < 15) {
        const int i = 30 - g;
        const float4 a = xw4[i * 16 + v];
        float4* o = og + (ptrdiff_t)(rowstart(i) - i - 1) * 16 + v;
        #pragma unroll 4
        for (int j = i + 1; j < FF; ++j)
            __stcs(o + j * 16, fmul4(a, xs4[j * 16 + v]));
    }
}

__global__ __launch_bounds__(NTHREADS)
void bilinear_kernel(const float* __restrict__ x,
                     const float* __restrict__ W,
                     float* __restrict__ out)
{
    __shared__ float ws[EE * EE];          // 16 KB : W, loaded ONCE per block
    __shared__ float xsb[2][FF * EE];      // 16 KB : double-buffered x row tiles
    __shared__ float xw[FF * EE];          // 8 KB  : current xw tile

    const int tid = threadIdx.x;
    const int b0  = blockIdx.x * ROWS_PER_BLK;

    const int e0 = (tid & 15) * 4;
    const int f0 = (tid >> 4) * 2;
    const int v  = tid & 15;
    const int g  = tid >> 4;

    // ---- prologue: async-load x row 0 into buf0; coop-load W ----
    {
        const float4* xg = reinterpret_cast<const float4*>(x) + (size_t)b0 * (FF * EE / 4);
        uint32_t s0 = (uint32_t)__cvta_generic_to_shared(&xsb[0][0]);
        #pragma unroll
        for (int q = tid; q < FF * EE / 4; q += NTHREADS)
            cp_async16(s0 + q * 16, xg + q);
        cp_async_commit();

        const float4* wg = reinterpret_cast<const float4*>(W);
        float4* ws4 = reinterpret_cast<float4*>(ws);
        #pragma unroll
        for (int q = tid; q < EE * EE / 4; q += NTHREADS)
            ws4[q] = wg[q];

        cp_async_wait0();
    }
    __syncthreads();

    // ---- pipelined row loop ----
    for (int r = 0; r < ROWS_PER_BLK; ++r) {
        const int cur = r & 1;
        const float* xs = xsb[cur];

        // matmul: xw[f][e] = sum_k xs[f][k] * W[k][e]
        {
            float4 a0 = make_float4(0.f, 0.f, 0.f, 0.f);
            float4 a1 = make_float4(0.f, 0.f, 0.f, 0.f);
            const float* xr0 = xs +  f0      * EE;
            const float* xr1 = xs + (f0 + 1) * EE;

            #pragma unroll 8
            for (int k = 0; k < EE; ++k) {
                const float4 w = *reinterpret_cast<const float4*>(&ws[k * EE + e0]);
                const float xa = xr0[k];
                const float xb = xr1[k];
                a0.x += xa * w.x; a0.y += xa * w.y; a0.z += xa * w.z; a0.w += xa * w.w;
                a1.x += xb * w.x; a1.y += xb * w.y; a1.z += xb * w.z; a1.w += xb * w.w;
            }
            *reinterpret_cast<float4*>(&xw[ f0      * EE + e0]) = a0;
            *reinterpret_cast<float4*>(&xw[(f0 + 1) * EE + e0]) = a1;
        }
        __syncthreads();  // xw visible; prev row's store (reader of buf cur^1) long done

        // issue async load of next row into the other buffer; it lands
        // underneath this row's store phase.
        if (r + 1 < ROWS_PER_BLK) {
            const float4* xg = reinterpret_cast<const float4*>(x)
                             + (size_t)(b0 + r + 1) * (FF * EE / 4);
            uint32_t sn = (uint32_t)__cvta_generic_to_shared(&xsb[cur ^ 1][0]);
            #pragma unroll
            for (int q = tid; q < FF * EE / 4; q += NTHREADS)
                cp_async16(sn + q * 16, xg + q);
            cp_async_commit();
        }

        // store phase: out[b0+r, p, :] = xw[i_p] * xs[j_p]
        store_rows(reinterpret_cast<const float4*>(xw),
                   reinterpret_cast<const float4*>(xs),
                   reinterpret_cast<float4*>(out) + (size_t)(b0 + r) * NV4,
                   g, v);

        if (r + 1 < ROWS_PER_BLK) cp_async_wait0();
        __syncthreads();  // all stores done reading xw/xs[cur]; next buf ready
    }
}

extern "C" void kernel_launch(void* const* d_in, const int* in_sizes, int n_in,
                              void* d_out, int out_size)
{
    const float* x = (const float*)d_in[0]; // [8192, 32, 64]
    const float* W = (const float*)d_in[1]; // [64, 64]
    float* out = (float*)d_out;             // [8192, 496, 64]
    (void)in_sizes; (void)n_in; (void)out_size;

    bilinear_kernel<<<NBLK, NTHREADS>>>(x, W, out);
}

// round 10
// speedup vs baseline: 1.0958x; 1.0958x over previous
#include <cuda_runtime.h>
#include <cstdint>
#include <cstddef>

// x:   [B=8192, F=32, E=64] f32
// W:   [E=64, E=64] f32
// out: [B, P=496, E=64] f32,  out[b,p,:] = (x[b,i_p,:] @ W) * x[b,j_p,:]
// (i_p, j_p) = triu_indices(32, k=1), row-major pair order.

#define BB 8192
#define FF 32
#define EE 64
#define PP 496
#define NV4 (PP * (EE/4)) // 7936 float4 per batch row
#define NTHREADS 256
#define ROWS_PER_BLK 2

// pairs before row i: sum_{t<i} (31-t) = 31*i - i*(i-1)/2
__device__ __forceinline__ int rowstart(int i) {
    return 31 * i - (i * (i - 1)) / 2;
}

__device__ __forceinline__ float4 fmul4(float4 a, float4 c) {
    float4 r;
    r.x = a.x * c.x; r.y = a.y * c.y; r.z = a.z * c.z; r.w = a.w * c.w;
    return r;
}

// Store one batch row: 16 groups of 16 lanes; group g owns rows i1=g
// (31-g pairs) and i2=30-g (g+1 pairs); g==15 owns only row 15 (balanced:
// 32 pairs/group). Inner body: 1 LDS.128 + 1 STG.128; each group streams
// sequential 256B pair records (8KB region) -> perfect coalescing.
__device__ __forceinline__ void store_rows(const float4* __restrict__ xw4,
                                           const float4* __restrict__ xs4,
                                           float4* __restrict__ og,
                                           int g, int v)
{
    {
        const int i = g;
        const float4 a = xw4[i * 16 + v];
        float4* o = og + (ptrdiff_t)(rowstart(i) - i - 1) * 16 + v;
        #pragma unroll 4
        for (int j = i + 1; j < FF; ++j)
            __stcs(o + j * 16, fmul4(a, xs4[j * 16 + v]));
    }
    if (g < 15) {
        const int i = 30 - g;
        const float4 a = xw4[i * 16 + v];
        float4* o = og + (ptrdiff_t)(rowstart(i) - i - 1) * 16 + v;
        #pragma unroll 4
        for (int j = i + 1; j < FF; ++j)
            __stcs(o + j * 16, fmul4(a, xs4[j * 16 + v]));
    }
}

__global__ __launch_bounds__(NTHREADS)
void bilinear_kernel(const float* __restrict__ x,
                     const float* __restrict__ W,
                     float* __restrict__ out)
{
    __shared__ float xs[ROWS_PER_BLK * FF * EE]; // 16 KB : x[b0], x[b0+1]
    __shared__ float ws[EE * EE];                // 16 KB : W
    __shared__ float xw[ROWS_PER_BLK * FF * EE]; //  8+8 KB? no: 2*32*64*4 = 16 KB
    // note: xw is 16 KB; total smem = 48 KB? -> too much for 4 CTAs at 228KB? 4*48=192 OK.

    const int tid = threadIdx.x;
    const int b0  = blockIdx.x * ROWS_PER_BLK;

    // ---- load x rows (1024 float4) and W (1024 float4) into SMEM ----
    {
        const float4* xg = reinterpret_cast<const float4*>(x) + (size_t)b0 * (FF * EE / 4);
        float4* xs4 = reinterpret_cast<float4*>(xs);
        #pragma unroll
        for (int q = tid; q < ROWS_PER_BLK * FF * EE / 4; q += NTHREADS)
            xs4[q] = xg[q];

        const float4* wg = reinterpret_cast<const float4*>(W);
        float4* ws4 = reinterpret_cast<float4*>(ws);
        #pragma unroll
        for (int q = tid; q < EE * EE / 4; q += NTHREADS)
            ws4[q] = wg[q];
    }

    __syncthreads();

    // ---- matmul: xw[r][f][e] = sum_k xs[r][f][k] * W[k][e] ----
    // 256 threads: 2 f-rows x 4 e-cols x 2 batch rows each; every w float4
    // feeds 4 FMA4s. xw has its own buffer -> no mid-matmul barrier needed.
    const int e0 = (tid & 15) * 4;
    const int f0 = (tid >> 4) * 2;
    {
        float4 a00 = make_float4(0.f, 0.f, 0.f, 0.f);
        float4 a01 = make_float4(0.f, 0.f, 0.f, 0.f);
        float4 a10 = make_float4(0.f, 0.f, 0.f, 0.f);
        float4 a11 = make_float4(0.f, 0.f, 0.f, 0.f);

        const float* xs0 = xs;
        const float* xs1 = xs + FF * EE;

        #pragma unroll 8
        for (int k = 0; k < EE; ++k) {
            const float4 w = *reinterpret_cast<const float4*>(&ws[k * EE + e0]);
            const float x00 = xs0[ f0      * EE + k];
            const float x01 = xs0[(f0 + 1) * EE + k];
            const float x10 = xs1[ f0      * EE + k];
            const float x11 = xs1[(f0 + 1) * EE + k];
            a00.x += x00 * w.x; a00.y += x00 * w.y; a00.z += x00 * w.z; a00.w += x00 * w.w;
            a01.x += x01 * w.x; a01.y += x01 * w.y; a01.z += x01 * w.z; a01.w += x01 * w.w;
            a10.x += x10 * w.x; a10.y += x10 * w.y; a10.z += x10 * w.z; a10.w += x10 * w.w;
            a11.x += x11 * w.x; a11.y += x11 * w.y; a11.z += x11 * w.z; a11.w += x11 * w.w;
        }

        *reinterpret_cast<float4*>(&xw[          f0      * EE + e0]) = a00;
        *reinterpret_cast<float4*>(&xw[         (f0 + 1) * EE + e0]) = a01;
        *reinterpret_cast<float4*>(&xw[FF * EE +  f0      * EE + e0]) = a10;
        *reinterpret_cast<float4*>(&xw[FF * EE + (f0 + 1) * EE + e0]) = a11;
    }

    __syncthreads();  // single barrier between compute and store

    // ---- store phase: out[b,p,e] = xw[i_p][e] * xs[j_p][e], both rows ----
    {
        const int v = tid & 15;
        const int g = tid >> 4;

        float4* og0 = reinterpret_cast<float4*>(out) + (size_t)b0 * NV4;

        store_rows(reinterpret_cast<const float4*>(xw),
                   reinterpret_cast<const float4*>(xs), og0, g, v);
        store_rows(reinterpret_cast<const float4*>(xw + FF * EE),
                   reinterpret_cast<const float4*>(xs + FF * EE), og0 + NV4, g, v);
    }
}

extern "C" void kernel_launch(void* const* d_in, const int* in_sizes, int n_in,
                              void* d_out, int out_size)
{
    const float* x = (const float*)d_in[0]; // [8192, 32, 64]
    const float* W = (const float*)d_in[1]; // [64, 64]
    float* out = (float*)d_out;             // [8192, 496, 64]
    (void)in_sizes; (void)n_in; (void)out_size;

    bilinear_kernel<<<BB / ROWS_PER_BLK, NTHREADS>>>(x, W, out);
}